// round 4
// baseline (speedup 1.0000x reference)
#include <cuda_runtime.h>
#include <cstdint>

#define H      100
#define NBATCH 4096
#define SEQ    512
#define TB     32
#define NBLK   (NBATCH / TB)   // 128
#define NTHREADS 800           // 50 hp-groups * 16 batch-groups (25 warps)

// smem: Wp [100][2][100] float2 (type-paired)
//       Hd [2][100][32]  float2 (h duplicated (h,h), batch-interleaved, double buffered)
#define WP_F2 (100 * 2 * 100)  // 20000 float2
#define HD_F2 (100 * 32)       // 3200 float2 per buffer
#define SMEM_BYTES ((WP_F2 + 2 * HD_F2) * 8)  // 211,200 B

typedef unsigned long long u64;

__device__ __forceinline__ void fma2(u64 &d, u64 a, u64 b) {
    asm("fma.rn.f32x2 %0, %1, %2, %0;" : "+l"(d) : "l"(a), "l"(b));
}
__device__ __forceinline__ u64 pk(float x, float y) {
    u64 r; asm("mov.b64 %0, {%1, %2};" : "=l"(r) : "f"(x), "f"(y)); return r;
}
__device__ __forceinline__ float2 upk(u64 v) {
    float2 r; asm("mov.b64 {%0, %1}, %2;" : "=f"(r.x), "=f"(r.y) : "l"(v)); return r;
}
__device__ __forceinline__ float sigf(float v) {
    return __fdividef(1.0f, 1.0f + __expf(-v));
}
__device__ __forceinline__ float tanhfast(float v) {
    return __fdividef(2.0f, 1.0f + __expf(-2.0f * v)) - 1.0f;
}

__global__ void __launch_bounds__(NTHREADS, 1)
lstm_kernel(const float* __restrict__ x,     // [512][4096]
            const float* __restrict__ Wih,   // [400]
            const float* __restrict__ Whh,   // [400][100]
            const float* __restrict__ bih,   // [400]
            const float* __restrict__ bhh,   // [400]
            const float* __restrict__ Wlin,  // [100]
            const float* __restrict__ blin,  // [1]
            float* __restrict__ out)         // [4096]
{
    extern __shared__ u64 sm[];
    u64* Wp = sm;            // [ (k*2 + tp) * 100 + hu ]
    u64* Hd = sm + WP_F2;    // [ buf*HD_F2 + k*32 + col ], col(b) = (b&1)*16 + (b>>1)

    const int tid = threadIdx.x;
    const int hp  = tid >> 4;   // 0..49 (hidden pair, covers hu 0..99 exactly)
    const int bg  = tid & 15;   // 0..15 (batch group of 2)

    // ---- Stage W_hh into type-paired smem layout ----
    // Wp[k][tp][hu] = ( W_hh[(2tp+0)*100+hu][k], W_hh[(2tp+1)*100+hu][k] )
    for (int idx = tid; idx < WP_F2; idx += NTHREADS) {
        int hu = idx % 100;
        int tp = (idx / 100) & 1;
        int k  = idx / 200;
        float wx = Whh[((tp * 2 + 0) * 100 + hu) * 100 + k];
        float wy = Whh[((tp * 2 + 1) * 100 + hu) * 100 + k];
        Wp[idx] = pk(wx, wy);
    }
    // zero both h buffers (h0 = 0)
    for (int idx = tid; idx < 2 * HD_F2; idx += NTHREADS)
        Hd[idx] = 0ull;

    // ---- per-thread constants: bias sums and W_ih for my 8 gate rows ----
    float bs[8], wi[8];  // [u*4 + type], types: 0=i 1=f 2=g 3=o
    #pragma unroll
    for (int u = 0; u < 2; u++) {
        int hu = 2 * hp + u;
        #pragma unroll
        for (int ty = 0; ty < 4; ty++) {
            int j = ty * 100 + hu;
            bs[u * 4 + ty] = bih[j] + bhh[j];
            wi[u * 4 + ty] = Wih[j];
        }
    }
    float c[4];  // cell state [u*2 + i]
    #pragma unroll
    for (int q = 0; q < 4; q++) c[q] = 0.f;

    const int bbase = blockIdx.x * TB + bg * 2;  // my two batches: bbase, bbase+1
    __syncthreads();

    // ---- recurrence over 512 steps ----
    for (int t = 0; t < SEQ; t++) {
        const u64* hcur = Hd + ((t & 1) ? HD_F2 : 0);
        u64*       hnxt = Hd + ((t & 1) ? 0 : HD_F2);

        // x for my 2 batches (consumed only in epilogue -> latency hidden)
        float2 xv = *(const float2*)(x + (size_t)t * NBATCH + bbase);

        u64 accA[2][2], accB[2][2];  // accA[u][i] = (i,f) gates; accB = (g,o)
        #pragma unroll
        for (int u = 0; u < 2; u++)
            #pragma unroll
            for (int i = 0; i < 2; i++) { accA[u][i] = 0ull; accB[u][i] = 0ull; }

        #pragma unroll 5
        for (int k = 0; k < H; k++) {
            // W for hidden units 2hp, 2hp+1 : one LDS.128 per type-pair row
            const ulonglong2 wA = *(const ulonglong2*)(Wp + (k * 2 + 0) * 100 + 2 * hp);
            const ulonglong2 wB = *(const ulonglong2*)(Wp + (k * 2 + 1) * 100 + 2 * hp);
            u64 h0 = hcur[k * 32 + bg];        // (h,h) for batch bbase+0
            u64 h1 = hcur[k * 32 + 16 + bg];   // (h,h) for batch bbase+1
            fma2(accA[0][0], wA.x, h0);
            fma2(accA[0][1], wA.x, h1);
            fma2(accA[1][0], wA.y, h0);
            fma2(accA[1][1], wA.y, h1);
            fma2(accB[0][0], wB.x, h0);
            fma2(accB[0][1], wB.x, h1);
            fma2(accB[1][0], wB.y, h0);
            fma2(accB[1][1], wB.y, h1);
        }

        // ---- epilogue: gates -> activations -> c,h update ----
        #pragma unroll
        for (int u = 0; u < 2; u++) {
            int hu = 2 * hp + u;
            #pragma unroll
            for (int i = 0; i < 2; i++) {
                float xb = (i == 0) ? xv.x : xv.y;
                float2 aA = upk(accA[u][i]);  // (i_gate, f_gate) pre-act
                float2 aB = upk(accB[u][i]);  // (g_gate, o_gate) pre-act
                float gi = aA.x + bs[u * 4 + 0] + wi[u * 4 + 0] * xb;
                float gf = aA.y + bs[u * 4 + 1] + wi[u * 4 + 1] * xb;
                float gg = aB.x + bs[u * 4 + 2] + wi[u * 4 + 2] * xb;
                float go = aB.y + bs[u * 4 + 3] + wi[u * 4 + 3] * xb;
                float si = sigf(gi);
                float sf = sigf(gf);
                float so = sigf(go);
                float tg = tanhfast(gg);
                float cn = sf * c[u * 2 + i] + si * tg;
                c[u * 2 + i] = cn;
                float hn = so * tanhfast(cn);
                hnxt[hu * 32 + i * 16 + bg] = pk(hn, hn);
            }
        }
        __syncthreads();
    }

    // ---- linear head: out[b] = h_T[b] . W_lin + b_lin ----
    if (tid < TB) {
        const u64* hfin = Hd;                 // SEQ even -> buffer 0
        int b = tid;
        int col = (b & 1) * 16 + (b >> 1);
        float acc = blin[0];
        #pragma unroll 4
        for (int k = 0; k < H; k++) {
            float2 hv = upk(hfin[k * 32 + col]);
            acc += hv.x * __ldg(Wlin + k);
        }
        out[blockIdx.x * TB + b] = acc;
    }
}

extern "C" void kernel_launch(void* const* d_in, const int* in_sizes, int n_in,
                              void* d_out, int out_size) {
    const float* x    = (const float*)d_in[0];
    const float* Wih  = (const float*)d_in[1];
    const float* Whh  = (const float*)d_in[2];
    const float* bih  = (const float*)d_in[3];
    const float* bhh  = (const float*)d_in[4];
    const float* Wlin = (const float*)d_in[5];
    const float* blin = (const float*)d_in[6];

    cudaFuncSetAttribute(lstm_kernel, cudaFuncAttributeMaxDynamicSharedMemorySize, SMEM_BYTES);
    lstm_kernel<<<NBLK, NTHREADS, SMEM_BYTES>>>(x, Wih, Whh, bih, bhh, Wlin, blin,
                                                (float*)d_out);
}

// round 5
// speedup vs baseline: 1.2993x; 1.2993x over previous
#include <cuda_runtime.h>
#include <cstdint>

#define H      100
#define NBATCH 4096
#define SEQ    512
#define TB     32
#define NBLK   (NBATCH / TB)   // 128
#define NTHREADS 200           // 50 hp-groups * 4 batch-groups (6.25 warps)

// smem: Wp [100][200] u64 : Wp[k*200 + hp*4 + ty] = (W[ty*100+2hp][k], W[ty*100+2hp+1][k])
//       Hd [2][100*32] float : plain h, double buffered
#define WP_F2   (100 * 200)            // 20000 u64 = 160,000 B
#define HD_F    (100 * 32)             // 3200 floats per buffer
#define SMEM_BYTES (WP_F2 * 8 + 2 * HD_F * 4)  // 185,600 B

typedef unsigned long long u64;

__device__ __forceinline__ void fma2(u64 &d, u64 a, u64 b) {
    asm("fma.rn.f32x2 %0, %1, %2, %0;" : "+l"(d) : "l"(a), "l"(b));
}
__device__ __forceinline__ u64 pk(float x, float y) {
    u64 r; asm("mov.b64 %0, {%1, %2};" : "=l"(r) : "f"(x), "f"(y)); return r;
}
__device__ __forceinline__ float2 upk(u64 v) {
    float2 r; asm("mov.b64 {%0, %1}, %2;" : "=f"(r.x), "=f"(r.y) : "l"(v)); return r;
}
__device__ __forceinline__ float tanh_mufu(float v) {
    float r; asm("tanh.approx.f32 %0, %1;" : "=f"(r) : "f"(v)); return r;
}
__device__ __forceinline__ float sig_mufu(float v) {
    return fmaf(0.5f, tanh_mufu(0.5f * v), 0.5f);
}

__global__ void __launch_bounds__(NTHREADS, 1)
lstm_kernel(const float* __restrict__ x,     // [512][4096]
            const float* __restrict__ Wih,   // [400]
            const float* __restrict__ Whh,   // [400][100]
            const float* __restrict__ bih,   // [400]
            const float* __restrict__ bhh,   // [400]
            const float* __restrict__ Wlin,  // [100]
            const float* __restrict__ blin,  // [1]
            float* __restrict__ out)         // [4096]
{
    extern __shared__ u64 sm[];
    u64*   Wp = sm;                         // [k*200 + hp*4 + ty]
    float* Hd = (float*)(sm + WP_F2);       // [buf*HD_F + k*32 + b]

    const int tid = threadIdx.x;
    const int hp  = tid >> 2;   // 0..49  (hidden pair: hu 2hp, 2hp+1)
    const int bg  = tid & 3;    // 0..3   (batch group of 8)

    // ---- Stage W_hh: pairs over adjacent hidden units, per gate type ----
    for (int idx = tid; idx < WP_F2; idx += NTHREADS) {
        int k  = idx / 200;
        int q  = idx % 200;
        int ph = q >> 2;
        int ty = q & 3;
        int row0 = ty * 100 + 2 * ph;
        Wp[idx] = pk(Whh[row0 * 100 + k], Whh[(row0 + 1) * 100 + k]);
    }
    // zero both h buffers (h0 = 0)
    for (int idx = tid; idx < 2 * HD_F; idx += NTHREADS)
        Hd[idx] = 0.f;

    // ---- per-thread constants: bias sums + W_ih for my 8 gate rows ----
    float bs[2][4], wi[2][4];  // [u][ty], types: 0=i 1=f 2=g 3=o
    #pragma unroll
    for (int u = 0; u < 2; u++) {
        int hu = 2 * hp + u;
        #pragma unroll
        for (int ty = 0; ty < 4; ty++) {
            int j = ty * 100 + hu;
            bs[u][ty] = bih[j] + bhh[j];
            wi[u][ty] = Wih[j];
        }
    }
    float c[2][8];  // cell state [u][b]
    #pragma unroll
    for (int u = 0; u < 2; u++)
        #pragma unroll
        for (int b = 0; b < 8; b++) c[u][b] = 0.f;

    const int bbase = blockIdx.x * TB + bg * 8;  // my 8 batches
    __syncthreads();

    // ---- recurrence over 512 steps ----
    for (int t = 0; t < SEQ; t++) {
        const float* hcur = Hd + ((t & 1) ? HD_F : 0);
        float*       hnxt = Hd + ((t & 1) ? 0 : HD_F);

        // x for my 8 batches (consumed only in epilogue -> latency hidden)
        float4 xv0 = *(const float4*)(x + (size_t)t * NBATCH + bbase);
        float4 xv1 = *(const float4*)(x + (size_t)t * NBATCH + bbase + 4);

        u64 acc[4][8];  // acc[ty][b] = f32x2 over (hu 2hp, 2hp+1)
        #pragma unroll
        for (int ty = 0; ty < 4; ty++)
            #pragma unroll
            for (int b = 0; b < 8; b++) acc[ty][b] = 0ull;

        #pragma unroll 2
        for (int k = 0; k < H; k++) {
            const ulonglong2 w01 = *(const ulonglong2*)(Wp + k * 200 + hp * 4);      // ty 0,1
            const ulonglong2 w23 = *(const ulonglong2*)(Wp + k * 200 + hp * 4 + 2);  // ty 2,3
            const float4 h0 = *(const float4*)(hcur + k * 32 + bg * 8);
            const float4 h1 = *(const float4*)(hcur + k * 32 + bg * 8 + 4);
            u64 hd[8];
            hd[0] = pk(h0.x, h0.x); hd[1] = pk(h0.y, h0.y);
            hd[2] = pk(h0.z, h0.z); hd[3] = pk(h0.w, h0.w);
            hd[4] = pk(h1.x, h1.x); hd[5] = pk(h1.y, h1.y);
            hd[6] = pk(h1.z, h1.z); hd[7] = pk(h1.w, h1.w);
            #pragma unroll
            for (int b = 0; b < 8; b++) {
                fma2(acc[0][b], w01.x, hd[b]);
                fma2(acc[1][b], w01.y, hd[b]);
                fma2(acc[2][b], w23.x, hd[b]);
                fma2(acc[3][b], w23.y, hd[b]);
            }
        }

        // ---- epilogue: gates -> activations -> c,h update ----
        float hn[2][8];
        #pragma unroll
        for (int b = 0; b < 8; b++) {
            float xb = (b < 4) ? ((b == 0) ? xv0.x : (b == 1) ? xv0.y : (b == 2) ? xv0.z : xv0.w)
                               : ((b == 4) ? xv1.x : (b == 5) ? xv1.y : (b == 6) ? xv1.z : xv1.w);
            float2 gI = upk(acc[0][b]);
            float2 gF = upk(acc[1][b]);
            float2 gG = upk(acc[2][b]);
            float2 gO = upk(acc[3][b]);
            #pragma unroll
            for (int u = 0; u < 2; u++) {
                float vi = (u ? gI.y : gI.x) + fmaf(wi[u][0], xb, bs[u][0]);
                float vf = (u ? gF.y : gF.x) + fmaf(wi[u][1], xb, bs[u][1]);
                float vg = (u ? gG.y : gG.x) + fmaf(wi[u][2], xb, bs[u][2]);
                float vo = (u ? gO.y : gO.x) + fmaf(wi[u][3], xb, bs[u][3]);
                float si = sig_mufu(vi);
                float sf = sig_mufu(vf);
                float so = sig_mufu(vo);
                float tg = tanh_mufu(vg);
                float cn = fmaf(sf, c[u][b], si * tg);
                c[u][b] = cn;
                hn[u][b] = so * tanh_mufu(cn);
            }
        }
        // vectorized h store: batches contiguous
        #pragma unroll
        for (int u = 0; u < 2; u++) {
            int hu = 2 * hp + u;
            float4 s0 = make_float4(hn[u][0], hn[u][1], hn[u][2], hn[u][3]);
            float4 s1 = make_float4(hn[u][4], hn[u][5], hn[u][6], hn[u][7]);
            *(float4*)(hnxt + hu * 32 + bg * 8)     = s0;
            *(float4*)(hnxt + hu * 32 + bg * 8 + 4) = s1;
        }
        __syncthreads();
    }

    // ---- linear head: out[b] = h_T[b] . W_lin + b_lin ----
    if (tid < TB) {
        const float* hfin = Hd;  // SEQ even -> final state in buffer 0
        float acc = blin[0];
        #pragma unroll 4
        for (int k = 0; k < H; k++)
            acc = fmaf(hfin[k * 32 + tid], __ldg(Wlin + k), acc);
        out[blockIdx.x * TB + tid] = acc;
    }
}

extern "C" void kernel_launch(void* const* d_in, const int* in_sizes, int n_in,
                              void* d_out, int out_size) {
    const float* x    = (const float*)d_in[0];
    const float* Wih  = (const float*)d_in[1];
    const float* Whh  = (const float*)d_in[2];
    const float* bih  = (const float*)d_in[3];
    const float* bhh  = (const float*)d_in[4];
    const float* Wlin = (const float*)d_in[5];
    const float* blin = (const float*)d_in[6];

    cudaFuncSetAttribute(lstm_kernel, cudaFuncAttributeMaxDynamicSharedMemorySize, SMEM_BYTES);
    lstm_kernel<<<NBLK, NTHREADS, SMEM_BYTES>>>(x, Wih, Whh, bih, bhh, Wlin, blin,
                                                (float*)d_out);
}